// round 13
// baseline (speedup 1.0000x reference)
#include <cuda_runtime.h>

// SpringMass: B=4096 independent 2-state linear ODEs, T=4096 RK4 steps each.
// Affine scan over time (pass1 compose / pass2 scan / pass3 replay).
//
// R13 = R12 (cp.async depth-2 quarter pipeline + state-apply cross-warp scan)
// + persistent CTAs: grid 1366 (< 1-wave capacity at 11 CTAs/SM), 3 rows per
// CTA as one flat 12-quarter pipeline (prefetch crosses row boundaries, carry
// state resets per row). Removes 2 wave transitions, the 0.52-wave tail, and
// 2/3 of pipeline-fill prologues. Pass1 identity-compose peeled.

#define T_LEN   4096
#define NTHR    128
#define ROWS    3                 // rows per persistent CTA
#define QSTEPS  1024              // steps per quarter
#define QPERROW 4
#define F4Q     4                 // input float4 per thread per quarter
#define O4Q     2                 // output float4 per thread per quarter
#define SSTR    5                 // padded float4 stride per chunk
#define TILEF4  (NTHR * SSTR)     // 640 float4 = 10.24 KB per buffer

namespace sm_consts {
constexpr double Cd = 0.1, dd = 0.01;
// A = alpha(k)*I + beta(k)*B, B=[[-C,-k],[1,0]] (deg-4 Taylor of exp(dt B))
constexpr double AL1d = -dd*dd/2.0 + Cd*dd*dd*dd/6.0 - Cd*Cd*dd*dd*dd*dd/24.0;
constexpr double AL2d = dd*dd*dd*dd/24.0;
constexpr double BE0d = dd - Cd*dd*dd/2.0 + Cd*Cd*dd*dd*dd/6.0 - Cd*Cd*Cd*dd*dd*dd*dd/24.0;
constexpr double BE1d = -dd*dd*dd/6.0 + Cd*dd*dd*dd*dd/12.0;
// forcing: g = c0*e1 + c1*B*e1, B*e1 = (-C,1)
constexpr double C00 = dd;
constexpr double C01 = dd*(-dd*dd/6.0 + dd*dd*dd*Cd/24.0);
constexpr double C10 = dd*(dd/2.0 - dd*dd*Cd/6.0 + dd*dd*dd*Cd*Cd/24.0);
constexpr double C11 = dd*(-dd*dd*dd/24.0);

constexpr float AL1 = (float)AL1d;
constexpr float AL2 = (float)AL2d;
constexpr float BE0 = (float)BE0d;
constexpr float BE1 = (float)BE1d;
constexpr float KG10 = (float)(C00 - Cd*C10);   // g1 = KG10 + KG11*k
constexpr float KG11 = (float)(C01 - Cd*C11);
constexpr float KG20 = (float)C10;              // g2 = KG20 + KG21*k
constexpr float KG21 = (float)C11;
constexpr float CF   = 0.1f;
}  // namespace sm_consts

struct Aff { float a11, a12, a21, a22, b1, b2; };

__device__ __forceinline__ Aff compose(const Aff& n, const Aff& o) {
    Aff r;
    r.a11 = fmaf(n.a11, o.a11, n.a12 * o.a21);
    r.a12 = fmaf(n.a11, o.a12, n.a12 * o.a22);
    r.a21 = fmaf(n.a21, o.a11, n.a22 * o.a21);
    r.a22 = fmaf(n.a21, o.a12, n.a22 * o.a22);
    r.b1  = fmaf(n.a11, o.b1, fmaf(n.a12, o.b2, n.b1));
    r.b2  = fmaf(n.a21, o.b1, fmaf(n.a22, o.b2, n.b2));
    return r;
}

// apply affine map to state: s' = A s + b   (4 FMA)
__device__ __forceinline__ void apply(const Aff& m, float& v, float& x) {
    float vn = fmaf(m.a11, v, fmaf(m.a12, x, m.b1));
    float xn = fmaf(m.a21, v, fmaf(m.a22, x, m.b2));
    v = vn; x = xn;
}

__device__ __forceinline__ Aff step_map(float k, float F) {
    using namespace sm_consts;
    Aff s;
    float al = fmaf(fmaf(AL2, k, AL1), k, 1.0f);
    float be = fmaf(BE1, k, BE0);
    s.a11 = fmaf(-CF, be, al);
    s.a12 = -k * be;
    s.a21 = be;
    s.a22 = al;
    s.b1 = F * fmaf(KG11, k, KG10);
    s.b2 = F * fmaf(KG21, k, KG20);
    return s;
}

// advance state, return xddot for this step (computed from NEW state)
__device__ __forceinline__ float step_state(float k, float F, float& v, float& x) {
    using namespace sm_consts;
    float al = fmaf(fmaf(AL2, k, AL1), k, 1.0f);
    float be = fmaf(BE1, k, BE0);
    float A11 = fmaf(-CF, be, al);
    float A12 = -k * be;
    float g1  = fmaf(KG11, k, KG10);
    float g2  = fmaf(KG21, k, KG20);
    float vn = fmaf(A11, v, fmaf(A12, x, F * g1));
    float xn = fmaf(be,  v, fmaf(al,  x, F * g2));
    v = vn; x = xn;
    return fmaf(-k, xn, fmaf(-CF, vn, F));
}

__device__ __forceinline__ Aff shfl_up_aff(const Aff& m, int off) {
    Aff r;
    r.a11 = __shfl_up_sync(0xffffffffu, m.a11, off);
    r.a12 = __shfl_up_sync(0xffffffffu, m.a12, off);
    r.a21 = __shfl_up_sync(0xffffffffu, m.a21, off);
    r.a22 = __shfl_up_sync(0xffffffffu, m.a22, off);
    r.b1  = __shfl_up_sync(0xffffffffu, m.b1,  off);
    r.b2  = __shfl_up_sync(0xffffffffu, m.b2,  off);
    return r;
}

// padded smem slot for (chunk c, float4 offset o); stride 5 keeps the 8-lane
// LDS.128 phases of chunk reads conflict-free.
__device__ __forceinline__ int slot(int c, int o) {
    return c * SSTR + o;
}

__device__ __forceinline__ void cp16(float4* smem_dst, const float4* gsrc) {
    unsigned s = (unsigned)__cvta_generic_to_shared(smem_dst);
    asm volatile("cp.async.cg.shared.global [%0], [%1], 16;" :: "r"(s), "l"(gsrc));
}
__device__ __forceinline__ void cp_commit() {
    asm volatile("cp.async.commit_group;" ::: "memory");
}
template <int N>
__device__ __forceinline__ void cp_wait() {
    asm volatile("cp.async.wait_group %0;" :: "n"(N) : "memory");
}

// prefetch quarter t (global quarter index within this CTA's row set)
__device__ __forceinline__ void prefetch_quarter(const float4* gin0, long rowspan,
                                                 int t, float4* buf, int l) {
    const float4* g = gin0 + (long)(t >> 2) * rowspan + (t & 3) * (QSTEPS / 2);
#pragma unroll
    for (int r = 0; r < F4Q; r++) {
        int idx = r * NTHR + l;
        cp16(&buf[slot(idx >> 2, idx & 3)], &g[idx]);
    }
    cp_commit();
}

__global__ void __launch_bounds__(NTHR, 11)
spring_scan_kernel(const float* __restrict__ in,
                   const float* __restrict__ vinit,
                   const float* __restrict__ xinit,
                   float* __restrict__ out, int B) {
    __shared__ float4 buf2[2][TILEF4];     // double-buffered quarter tiles
    __shared__ Aff wsum[NTHR / 32];

    const int b0 = blockIdx.x * ROWS;
    const int nrows = min(ROWS, B - b0);
    const int nq = nrows * QPERROW;
    const int l = threadIdx.x;
    const int lane = l & 31;
    const int w = l >> 5;

    const float4* gin0  = reinterpret_cast<const float4*>(in + (long)b0 * T_LEN * 2);
    float4*       gout0 = reinterpret_cast<float4*>(out + (long)b0 * T_LEN);
    const long rowspan_in  = T_LEN / 2;    // float4 per row (input)
    const long rowspan_out = T_LEN / 4;    // float4 per row (output)

    // ---- Prologue: prefetch quarters 0 and 1 ----
    prefetch_quarter(gin0, rowspan_in, 0, buf2[0], l);
    prefetch_quarter(gin0, rowspan_in, 1, buf2[1], l);

    float vh = 0.f, xh = 0.f;

#pragma unroll 1
    for (int t = 0; t < nq; t++) {
        const int row = t >> 2;            // row within this CTA's set
        const int qr  = t & 3;             // quarter within row
        float4* buf = buf2[t & 1];
        float4* gout_q = gout0 + (long)row * rowspan_out + qr * (QSTEPS / 4);

        if (qr == 0) {                     // carry reset at row boundary
            vh = vinit[b0 + row];
            xh = xinit[b0 + row];
        }

        // wait for tile t (allow the t+1 group to stay in flight)
        if (t < nq - 1) cp_wait<1>(); else cp_wait<0>();
        __syncthreads();

        // ---- Pass 1: compose this thread's 8-step chunk map ----
        float4 d0 = buf[slot(l, 0)];
        Aff M = step_map(d0.x, d0.y);                  // peeled identity compose
        M = compose(step_map(d0.z, d0.w), M);
#pragma unroll
        for (int o = 1; o < F4Q; o++) {
            float4 d = buf[slot(l, o)];
            M = compose(step_map(d.x, d.y), M);
            M = compose(step_map(d.z, d.w), M);
        }

        // ---- Pass 2: warp scan of chunk maps ----
#pragma unroll
        for (int off = 1; off < 32; off <<= 1) {
            Aff o = shfl_up_aff(M, off);
            if (lane >= off) M = compose(M, o);
        }

        // exclusive in-warp map
        Aff eo = shfl_up_aff(M, 1);
        Aff excl;
        if (lane == 0) { excl.a11 = 1.f; excl.a12 = 0.f; excl.a21 = 0.f;
                         excl.a22 = 1.f; excl.b1 = 0.f;  excl.b2 = 0.f; }
        else           { excl = eo; }

        if (lane == 31) wsum[w] = M;
        __syncthreads();

        // ---- Cross-warp: run the carried STATE through warp-sum maps ----
        float sv = vh, sx = xh;            // running state
        float pv = vh, px = xh;            // state entering this warp
#pragma unroll
        for (int j = 0; j < NTHR / 32; j++) {
            if (j == w) { pv = sv; px = sx; }
            apply(wsum[j], sv, sx);
        }
        vh = sv; xh = sx;                  // carry: state entering next quarter

        // state entering this thread's chunk
        float v = pv, x = px;
        apply(excl, v, x);

        // ---- Pass 3: replay chunk, write xddot in place (thread-private) ----
#pragma unroll
        for (int j = 0; j < O4Q; j++) {
            float4 e0 = buf[slot(l, 2 * j)];
            float4 e1 = buf[slot(l, 2 * j + 1)];
            float4 o4;
            o4.x = step_state(e0.x, e0.y, v, x);
            o4.y = step_state(e0.z, e0.w, v, x);
            o4.z = step_state(e1.x, e1.y, v, x);
            o4.w = step_state(e1.z, e1.w, v, x);
            buf[slot(l, j)] = o4;
        }
        __syncthreads();                   // pass3 writes visible to drain

        // ---- Drain: padded smem -> coalesced global store ----
#pragma unroll
        for (int r = 0; r < O4Q; r++) {
            int idx = r * NTHR + l;
            gout_q[idx] = buf[slot(idx >> 1, idx & 1)];
        }

        // ---- Prefetch tile t+2 into this buffer (crosses row boundaries) ----
        if (t + 2 < nq) {
            __syncthreads();               // all drain LDS done before overwrite
            prefetch_quarter(gin0, rowspan_in, t + 2, buf, l);
        }
    }
}

extern "C" void kernel_launch(void* const* d_in, const int* in_sizes, int n_in,
                              void* d_out, int out_size) {
    const float* in = (const float*)d_in[0];       // (B, T, 2) float32
    const float* vi = (const float*)d_in[1];       // (B, 1)
    const float* xi = (const float*)d_in[2];       // (B, 1)
    float* out = (float*)d_out;                    // (B, T, 1) float32
    const int B = in_sizes[1];                     // 4096
    const int grid = (B + ROWS - 1) / ROWS;        // 1366: one resident wave
    spring_scan_kernel<<<grid, NTHR>>>(in, vi, xi, out, B);
}

// round 14
// speedup vs baseline: 1.0887x; 1.0887x over previous
#include <cuda_runtime.h>

// SpringMass: B=4096 independent 2-state linear ODEs, T=4096 RK4 steps each.
// Affine scan over time (pass1 compose / pass2 scan / pass3 replay).
//
// R14 = R12 (cp.async depth-2 quarter pipeline, grid 4096, state-apply
// cross-warp scan) + two scan-region cuts:
//  (1) exclusive prefix via STATE shuffle: each lane applies its inclusive
//      map to the warp-entry state (4 FMA) and the chunk-entry state comes
//      from a 2-field shfl_up of that state (replaces the 6-field map shfl
//      + apply; also shortens the serial shfl chain).
//  (2) pass1 identity-compose peeled.
// R13 persistence reverted: 1-wave persistent CTAs lost to per-CTA
// completion spread (occ 56->43%).

#define T_LEN   4096
#define NTHR    128
#define QSTEPS  1024              // steps per quarter
#define F4Q     4                 // input float4 per thread per quarter
#define O4Q     2                 // output float4 per thread per quarter
#define SSTR    5                 // padded float4 stride per chunk
#define TILEF4  (NTHR * SSTR)     // 640 float4 = 10.24 KB per buffer

namespace sm_consts {
constexpr double Cd = 0.1, dd = 0.01;
// A = alpha(k)*I + beta(k)*B, B=[[-C,-k],[1,0]] (deg-4 Taylor of exp(dt B))
constexpr double AL1d = -dd*dd/2.0 + Cd*dd*dd*dd/6.0 - Cd*Cd*dd*dd*dd*dd/24.0;
constexpr double AL2d = dd*dd*dd*dd/24.0;
constexpr double BE0d = dd - Cd*dd*dd/2.0 + Cd*Cd*dd*dd*dd/6.0 - Cd*Cd*Cd*dd*dd*dd*dd/24.0;
constexpr double BE1d = -dd*dd*dd/6.0 + Cd*dd*dd*dd*dd/12.0;
// forcing: g = c0*e1 + c1*B*e1, B*e1 = (-C,1)
constexpr double C00 = dd;
constexpr double C01 = dd*(-dd*dd/6.0 + dd*dd*dd*Cd/24.0);
constexpr double C10 = dd*(dd/2.0 - dd*dd*Cd/6.0 + dd*dd*dd*Cd*Cd/24.0);
constexpr double C11 = dd*(-dd*dd*dd/24.0);

constexpr float AL1 = (float)AL1d;
constexpr float AL2 = (float)AL2d;
constexpr float BE0 = (float)BE0d;
constexpr float BE1 = (float)BE1d;
constexpr float KG10 = (float)(C00 - Cd*C10);   // g1 = KG10 + KG11*k
constexpr float KG11 = (float)(C01 - Cd*C11);
constexpr float KG20 = (float)C10;              // g2 = KG20 + KG21*k
constexpr float KG21 = (float)C11;
constexpr float CF   = 0.1f;
}  // namespace sm_consts

struct Aff { float a11, a12, a21, a22, b1, b2; };

__device__ __forceinline__ Aff compose(const Aff& n, const Aff& o) {
    Aff r;
    r.a11 = fmaf(n.a11, o.a11, n.a12 * o.a21);
    r.a12 = fmaf(n.a11, o.a12, n.a12 * o.a22);
    r.a21 = fmaf(n.a21, o.a11, n.a22 * o.a21);
    r.a22 = fmaf(n.a21, o.a12, n.a22 * o.a22);
    r.b1  = fmaf(n.a11, o.b1, fmaf(n.a12, o.b2, n.b1));
    r.b2  = fmaf(n.a21, o.b1, fmaf(n.a22, o.b2, n.b2));
    return r;
}

// apply affine map to state: s' = A s + b   (4 FMA)
__device__ __forceinline__ void apply(const Aff& m, float& v, float& x) {
    float vn = fmaf(m.a11, v, fmaf(m.a12, x, m.b1));
    float xn = fmaf(m.a21, v, fmaf(m.a22, x, m.b2));
    v = vn; x = xn;
}

__device__ __forceinline__ Aff step_map(float k, float F) {
    using namespace sm_consts;
    Aff s;
    float al = fmaf(fmaf(AL2, k, AL1), k, 1.0f);
    float be = fmaf(BE1, k, BE0);
    s.a11 = fmaf(-CF, be, al);
    s.a12 = -k * be;
    s.a21 = be;
    s.a22 = al;
    s.b1 = F * fmaf(KG11, k, KG10);
    s.b2 = F * fmaf(KG21, k, KG20);
    return s;
}

// advance state, return xddot for this step (computed from NEW state)
__device__ __forceinline__ float step_state(float k, float F, float& v, float& x) {
    using namespace sm_consts;
    float al = fmaf(fmaf(AL2, k, AL1), k, 1.0f);
    float be = fmaf(BE1, k, BE0);
    float A11 = fmaf(-CF, be, al);
    float A12 = -k * be;
    float g1  = fmaf(KG11, k, KG10);
    float g2  = fmaf(KG21, k, KG20);
    float vn = fmaf(A11, v, fmaf(A12, x, F * g1));
    float xn = fmaf(be,  v, fmaf(al,  x, F * g2));
    v = vn; x = xn;
    return fmaf(-k, xn, fmaf(-CF, vn, F));
}

__device__ __forceinline__ Aff shfl_up_aff(const Aff& m, int off) {
    Aff r;
    r.a11 = __shfl_up_sync(0xffffffffu, m.a11, off);
    r.a12 = __shfl_up_sync(0xffffffffu, m.a12, off);
    r.a21 = __shfl_up_sync(0xffffffffu, m.a21, off);
    r.a22 = __shfl_up_sync(0xffffffffu, m.a22, off);
    r.b1  = __shfl_up_sync(0xffffffffu, m.b1,  off);
    r.b2  = __shfl_up_sync(0xffffffffu, m.b2,  off);
    return r;
}

// padded smem slot for (chunk c, float4 offset o); stride 5 keeps the 8-lane
// LDS.128 phases of chunk reads conflict-free.
__device__ __forceinline__ int slot(int c, int o) {
    return c * SSTR + o;
}

__device__ __forceinline__ void cp16(float4* smem_dst, const float4* gsrc) {
    unsigned s = (unsigned)__cvta_generic_to_shared(smem_dst);
    asm volatile("cp.async.cg.shared.global [%0], [%1], 16;" :: "r"(s), "l"(gsrc));
}
__device__ __forceinline__ void cp_commit() {
    asm volatile("cp.async.commit_group;" ::: "memory");
}
template <int N>
__device__ __forceinline__ void cp_wait() {
    asm volatile("cp.async.wait_group %0;" :: "n"(N) : "memory");
}

__global__ void __launch_bounds__(NTHR, 11)
spring_scan_kernel(const float* __restrict__ in,
                   const float* __restrict__ vinit,
                   const float* __restrict__ xinit,
                   float* __restrict__ out) {
    __shared__ float4 buf2[2][TILEF4];     // double-buffered quarter tiles
    __shared__ Aff wsum[NTHR / 32];

    const int b = blockIdx.x;
    const int l = threadIdx.x;
    const int lane = l & 31;
    const int w = l >> 5;

    const float4* gin  = reinterpret_cast<const float4*>(in + (long)b * T_LEN * 2);
    float4*       gout = reinterpret_cast<float4*>(out + (long)b * T_LEN);

    float vh = vinit[b], xh = xinit[b];    // state entering current quarter

    // ---- Prologue: prefetch quarters 0 and 1 ----
#pragma unroll
    for (int q = 0; q < 2; q++) {
        const float4* g = gin + q * (QSTEPS / 2);
        float4* buf = buf2[q];
#pragma unroll
        for (int r = 0; r < F4Q; r++) {
            int idx = r * NTHR + l;
            cp16(&buf[slot(idx >> 2, idx & 3)], &g[idx]);
        }
        cp_commit();
    }

#pragma unroll 1
    for (int q = 0; q < 4; q++) {
        float4* buf = buf2[q & 1];
        float4* gout_q = gout + q * (QSTEPS / 4);

        // wait for quarter q's tile (allow the q+1 group to stay in flight)
        if (q < 3) cp_wait<1>(); else cp_wait<0>();
        __syncthreads();

        // ---- Pass 1: compose this thread's 8-step chunk map ----
        float4 d0 = buf[slot(l, 0)];
        Aff M = step_map(d0.x, d0.y);                  // identity compose peeled
        M = compose(step_map(d0.z, d0.w), M);
#pragma unroll
        for (int o = 1; o < F4Q; o++) {
            float4 d = buf[slot(l, o)];
            M = compose(step_map(d.x, d.y), M);
            M = compose(step_map(d.z, d.w), M);
        }

        // ---- Pass 2: warp scan of chunk maps ----
#pragma unroll
        for (int off = 1; off < 32; off <<= 1) {
            Aff o = shfl_up_aff(M, off);
            if (lane >= off) M = compose(M, o);
        }

        if (lane == 31) wsum[w] = M;
        __syncthreads();

        // ---- Cross-warp: run the carried STATE through warp-sum maps ----
        float sv = vh, sx = xh;            // running state
        float pv = vh, px = xh;            // state entering this warp
#pragma unroll
        for (int j = 0; j < NTHR / 32; j++) {
            if (j == w) { pv = sv; px = sx; }
            apply(wsum[j], sv, sx);
        }
        vh = sv; xh = sx;                  // carry: state entering next quarter

        // ---- Chunk-entry state via STATE shuffle (not map shuffle) ----
        // z = state after MY chunk (inclusive map applied to warp entry);
        // lane l's entry state = lane l-1's z; lane 0 uses warp entry.
        float zv = pv, zx = px;
        apply(M, zv, zx);
        float uv = __shfl_up_sync(0xffffffffu, zv, 1);
        float ux = __shfl_up_sync(0xffffffffu, zx, 1);
        float v = (lane == 0) ? pv : uv;
        float x = (lane == 0) ? px : ux;

        // ---- Pass 3: replay chunk, write xddot in place (thread-private) ----
#pragma unroll
        for (int j = 0; j < O4Q; j++) {
            float4 e0 = buf[slot(l, 2 * j)];
            float4 e1 = buf[slot(l, 2 * j + 1)];
            float4 o4;
            o4.x = step_state(e0.x, e0.y, v, x);
            o4.y = step_state(e0.z, e0.w, v, x);
            o4.z = step_state(e1.x, e1.y, v, x);
            o4.w = step_state(e1.z, e1.w, v, x);
            buf[slot(l, j)] = o4;
        }
        __syncthreads();                   // pass3 writes visible to drain

        // ---- Drain: padded smem -> coalesced global store ----
#pragma unroll
        for (int r = 0; r < O4Q; r++) {
            int idx = r * NTHR + l;
            gout_q[idx] = buf[slot(idx >> 1, idx & 1)];
        }

        // ---- Prefetch quarter q+2 into this buffer (after drain reads) ----
        if (q < 2) {
            __syncthreads();               // all drain LDS done before overwrite
            const float4* g = gin + (q + 2) * (QSTEPS / 2);
#pragma unroll
            for (int r = 0; r < F4Q; r++) {
                int idx = r * NTHR + l;
                cp16(&buf[slot(idx >> 2, idx & 3)], &g[idx]);
            }
            cp_commit();
        }
    }
}

extern "C" void kernel_launch(void* const* d_in, const int* in_sizes, int n_in,
                              void* d_out, int out_size) {
    const float* in = (const float*)d_in[0];       // (B, T, 2) float32
    const float* vi = (const float*)d_in[1];       // (B, 1)
    const float* xi = (const float*)d_in[2];       // (B, 1)
    float* out = (float*)d_out;                    // (B, T, 1) float32
    const int B = in_sizes[1];                     // 4096
    spring_scan_kernel<<<B, NTHR>>>(in, vi, xi, out);
}

// round 15
// speedup vs baseline: 1.1748x; 1.0791x over previous
#include <cuda_runtime.h>

// SpringMass: B=4096 independent 2-state linear ODEs, T=4096 RK4 steps each.
// Affine scan over time (pass1 compose / pass2 scan / pass3 replay).
//
// R15: scan amortization. Scans now run at HALF granularity (16 steps/thread,
// 2 scans/row instead of 4: -340 instr/thread) while staging stays at QUARTER
// granularity via a ring of three 8KB buffers (every 16-step chunk lives
// entirely inside one quarter: threads 0-63 read buffer X, 64-127 buffer Y).
// Ring pipeline: Q0(h+1) prefetched a full half ahead into the third buffer;
// Q1(h+1) refills the freed X after drain. XOR swizzle o^F(c),
// F(c)=((c&1)<<2)|((c>>1)&3): conflict-free for staging, same-o chunk reads,
// in-place output writes, and pair-of-chunks drain reads (F flips bit2
// between adjacent chunks).

#define T_LEN   4096
#define NTHR    128
#define QF4     512               // float4 per quarter (1024 steps)
#define HO4     512               // output float4 per half (2048 steps)

namespace sm_consts {
constexpr double Cd = 0.1, dd = 0.01;
// A = alpha(k)*I + beta(k)*B, B=[[-C,-k],[1,0]] (deg-4 Taylor of exp(dt B))
constexpr double AL1d = -dd*dd/2.0 + Cd*dd*dd*dd/6.0 - Cd*Cd*dd*dd*dd*dd/24.0;
constexpr double AL2d = dd*dd*dd*dd/24.0;
constexpr double BE0d = dd - Cd*dd*dd/2.0 + Cd*Cd*dd*dd*dd/6.0 - Cd*Cd*Cd*dd*dd*dd*dd/24.0;
constexpr double BE1d = -dd*dd*dd/6.0 + Cd*dd*dd*dd*dd/12.0;
// forcing: g = c0*e1 + c1*B*e1, B*e1 = (-C,1)
constexpr double C00 = dd;
constexpr double C01 = dd*(-dd*dd/6.0 + dd*dd*dd*Cd/24.0);
constexpr double C10 = dd*(dd/2.0 - dd*dd*Cd/6.0 + dd*dd*dd*Cd*Cd/24.0);
constexpr double C11 = dd*(-dd*dd*dd/24.0);

constexpr float AL1 = (float)AL1d;
constexpr float AL2 = (float)AL2d;
constexpr float BE0 = (float)BE0d;
constexpr float BE1 = (float)BE1d;
constexpr float KG10 = (float)(C00 - Cd*C10);   // g1 = KG10 + KG11*k
constexpr float KG11 = (float)(C01 - Cd*C11);
constexpr float KG20 = (float)C10;              // g2 = KG20 + KG21*k
constexpr float KG21 = (float)C11;
constexpr float CF   = 0.1f;
}  // namespace sm_consts

struct Aff { float a11, a12, a21, a22, b1, b2; };

__device__ __forceinline__ Aff compose(const Aff& n, const Aff& o) {
    Aff r;
    r.a11 = fmaf(n.a11, o.a11, n.a12 * o.a21);
    r.a12 = fmaf(n.a11, o.a12, n.a12 * o.a22);
    r.a21 = fmaf(n.a21, o.a11, n.a22 * o.a21);
    r.a22 = fmaf(n.a21, o.a12, n.a22 * o.a22);
    r.b1  = fmaf(n.a11, o.b1, fmaf(n.a12, o.b2, n.b1));
    r.b2  = fmaf(n.a21, o.b1, fmaf(n.a22, o.b2, n.b2));
    return r;
}

// apply affine map to state: s' = A s + b   (4 FMA)
__device__ __forceinline__ void apply(const Aff& m, float& v, float& x) {
    float vn = fmaf(m.a11, v, fmaf(m.a12, x, m.b1));
    float xn = fmaf(m.a21, v, fmaf(m.a22, x, m.b2));
    v = vn; x = xn;
}

__device__ __forceinline__ Aff step_map(float k, float F) {
    using namespace sm_consts;
    Aff s;
    float al = fmaf(fmaf(AL2, k, AL1), k, 1.0f);
    float be = fmaf(BE1, k, BE0);
    s.a11 = fmaf(-CF, be, al);
    s.a12 = -k * be;
    s.a21 = be;
    s.a22 = al;
    s.b1 = F * fmaf(KG11, k, KG10);
    s.b2 = F * fmaf(KG21, k, KG20);
    return s;
}

// advance state, return xddot for this step (computed from NEW state)
__device__ __forceinline__ float step_state(float k, float F, float& v, float& x) {
    using namespace sm_consts;
    float al = fmaf(fmaf(AL2, k, AL1), k, 1.0f);
    float be = fmaf(BE1, k, BE0);
    float A11 = fmaf(-CF, be, al);
    float A12 = -k * be;
    float g1  = fmaf(KG11, k, KG10);
    float g2  = fmaf(KG21, k, KG20);
    float vn = fmaf(A11, v, fmaf(A12, x, F * g1));
    float xn = fmaf(be,  v, fmaf(al,  x, F * g2));
    v = vn; x = xn;
    return fmaf(-k, xn, fmaf(-CF, vn, F));
}

__device__ __forceinline__ Aff shfl_up_aff(const Aff& m, int off) {
    Aff r;
    r.a11 = __shfl_up_sync(0xffffffffu, m.a11, off);
    r.a12 = __shfl_up_sync(0xffffffffu, m.a12, off);
    r.a21 = __shfl_up_sync(0xffffffffu, m.a21, off);
    r.a22 = __shfl_up_sync(0xffffffffu, m.a22, off);
    r.b1  = __shfl_up_sync(0xffffffffu, m.b1,  off);
    r.b2  = __shfl_up_sync(0xffffffffu, m.b2,  off);
    return r;
}

// XOR swizzle for a quarter buffer: chunk cl (0..63) x float4 offset o (0..7).
// F is bijective on the 3 low chunk bits and flips bit2 between adjacent
// chunks -> conflict-free for every access phase used below.
__device__ __forceinline__ int Fsw(int c) {
    return ((c & 1) << 2) | ((c >> 1) & 3);
}
__device__ __forceinline__ int slot(int cl, int o) {
    return (cl << 3) | (o ^ Fsw(cl));
}

__device__ __forceinline__ void cp16(float4* smem_dst, const float4* gsrc) {
    unsigned s = (unsigned)__cvta_generic_to_shared(smem_dst);
    asm volatile("cp.async.cg.shared.global [%0], [%1], 16;" :: "r"(s), "l"(gsrc));
}
__device__ __forceinline__ void cp_commit() {
    asm volatile("cp.async.commit_group;" ::: "memory");
}
template <int N>
__device__ __forceinline__ void cp_wait() {
    asm volatile("cp.async.wait_group %0;" :: "n"(N) : "memory");
}

// stage one 8KB quarter (512 float4) into a ring buffer, coalesced
__device__ __forceinline__ void prefetch_q(float4* qb, const float4* gq, int l) {
#pragma unroll
    for (int r = 0; r < 4; r++) {
        int idx = r * NTHR + l;
        cp16(&qb[slot(idx >> 3, idx & 7)], &gq[idx]);
    }
    cp_commit();
}

__global__ void __launch_bounds__(NTHR, 9)
spring_scan_kernel(const float* __restrict__ in,
                   const float* __restrict__ vinit,
                   const float* __restrict__ xinit,
                   float* __restrict__ out) {
    __shared__ float4 ring[3][QF4];        // 3 x 8KB quarter buffers
    __shared__ Aff wsum[NTHR / 32];

    const int b = blockIdx.x;
    const int l = threadIdx.x;
    const int lane = l & 31;
    const int w = l >> 5;

    const float4* gin  = reinterpret_cast<const float4*>(in + (long)b * T_LEN * 2);
    float4*       gout = reinterpret_cast<float4*>(out + (long)b * T_LEN);

    float vh = vinit[b], xh = xinit[b];    // state entering current half

    // ---- Prologue: prefetch Q0,Q1 (half 0) and Q2 (=Q0 of half 1) ----
    prefetch_q(ring[0], gin,            l);
    prefetch_q(ring[1], gin + QF4,      l);
    prefetch_q(ring[2], gin + 2 * QF4,  l);

#pragma unroll 1
    for (int h = 0; h < 2; h++) {
        float4* X = (h == 0) ? ring[0] : ring[2];   // quarter with chunks 0-63
        float4* Y = (h == 0) ? ring[1] : ring[0];   // quarter with chunks 64-127
        float4* gout_h = gout + h * HO4;

        // wait for this half's two quarters (half 0: allow Q2 in flight)
        if (h == 0) cp_wait<1>(); else cp_wait<0>();
        __syncthreads();

        float4* mybuf = (l < 64) ? X : Y;
        const int cl = l & 63;
        const int base = cl << 3;
        const int f = Fsw(cl);

        // ---- Pass 1: compose this thread's 16-step chunk map ----
        float4 d0 = mybuf[base | (0 ^ f)];
        Aff M = step_map(d0.x, d0.y);              // identity compose peeled
        M = compose(step_map(d0.z, d0.w), M);
#pragma unroll
        for (int o = 1; o < 8; o++) {
            float4 d = mybuf[base | (o ^ f)];
            M = compose(step_map(d.x, d.y), M);
            M = compose(step_map(d.z, d.w), M);
        }

        // ---- Pass 2: warp scan of chunk maps ----
#pragma unroll
        for (int off = 1; off < 32; off <<= 1) {
            Aff o = shfl_up_aff(M, off);
            if (lane >= off) M = compose(M, o);
        }

        if (lane == 31) wsum[w] = M;
        __syncthreads();

        // ---- Cross-warp: run the carried STATE through warp-sum maps ----
        float sv = vh, sx = xh;            // running state
        float pv = vh, px = xh;            // state entering this warp
#pragma unroll
        for (int j = 0; j < NTHR / 32; j++) {
            if (j == w) { pv = sv; px = sx; }
            apply(wsum[j], sv, sx);
        }
        vh = sv; xh = sx;                  // carry: state entering next half

        // ---- Chunk-entry state via STATE shuffle ----
        float zv = pv, zx = px;
        apply(M, zv, zx);
        float uv = __shfl_up_sync(0xffffffffu, zv, 1);
        float ux = __shfl_up_sync(0xffffffffu, zx, 1);
        float v = (lane == 0) ? pv : uv;
        float x = (lane == 0) ? px : ux;

        // ---- Pass 3: replay 16 steps, write xddot in place ----
        // Output f4 j consumes input f4 2j,2j+1 (j <= 2j: already consumed).
#pragma unroll
        for (int j = 0; j < 4; j++) {
            float4 e0 = mybuf[base | ((2 * j) ^ f)];
            float4 e1 = mybuf[base | ((2 * j + 1) ^ f)];
            float4 o4;
            o4.x = step_state(e0.x, e0.y, v, x);
            o4.y = step_state(e0.z, e0.w, v, x);
            o4.z = step_state(e1.x, e1.y, v, x);
            o4.w = step_state(e1.z, e1.w, v, x);
            mybuf[base | (j ^ f)] = o4;
        }
        __syncthreads();                   // pass3 writes visible to drain

        // ---- Drain: swizzled smem -> coalesced global store ----
#pragma unroll
        for (int r = 0; r < 4; r++) {
            int idx = r * NTHR + l;        // output f4 index in half (0..511)
            int c = idx >> 2;              // owning chunk (uniform per r-warp)
            float4* db = (c < 64) ? X : Y;
            gout_h[idx] = db[slot(c & 63, idx & 3)];
        }

        // ---- Refill freed X with Q1 of half 1 ----
        if (h == 0) {
            __syncthreads();               // all drain reads done before overwrite
            prefetch_q(ring[0], gin + 3 * QF4, l);
        }
    }
}

extern "C" void kernel_launch(void* const* d_in, const int* in_sizes, int n_in,
                              void* d_out, int out_size) {
    const float* in = (const float*)d_in[0];       // (B, T, 2) float32
    const float* vi = (const float*)d_in[1];       // (B, 1)
    const float* xi = (const float*)d_in[2];       // (B, 1)
    float* out = (float*)d_out;                    // (B, T, 1) float32
    const int B = in_sizes[1];                     // 4096
    spring_scan_kernel<<<B, NTHR>>>(in, vi, xi, out);
}